// round 14
// baseline (speedup 1.0000x reference)
#include <cuda_runtime.h>
#include <cuda_bf16.h>
#include <cstdint>

// Problem constants.
constexpr int CDIM = 768;
constexpr int NHD  = 12;
constexpr int HD   = 64;
constexpr int WSZ  = 14;
constexpr int NT   = WSZ * WSZ;        // 196
constexpr int NWIN = 256;
constexpr int M1   = NWIN * NT;        // 50176
constexpr int QKVN = 3 * CDIM;         // 2304

// Attention padded dims (mma tiles of 16).
constexpr int MP = 224;                // query rows padded (14 x 16)
constexpr int NP = 208;                // key rows padded (13 x 16)

// GEMM tiling: CTA 128x128, K-chunk 32, 8 warps (4Mx2N), 3 stages.
constexpr int KCH = 32;
constexpr int NCH = CDIM / KCH;        // 24
constexpr int T_AHI = 0;
constexpr int T_ALO = 8192;
constexpr int T_BHI = 16384;
constexpr int T_BLO = 24576;
constexpr int STG_B = 32768;
constexpr int MB_OFF = 3 * STG_B;      // 6 mbarriers after the stages
constexpr int SMEM_TOT = MB_OFF + 64;  // 96 KB + 64

// Attention smem layout (bytes). Q is STAGED in the K/V region (phase 1),
// fragments extracted to registers, then the region is overwritten with
// K/V (phase 2). Peak = KV (104 KB) + table -> 2 CTAs/SM.
constexpr int A_KHI = 0;
constexpr int A_KLO = A_KHI + NP * 128;    // 26624
constexpr int A_VHI = A_KLO + NP * 128;    // 53248
constexpr int A_VLO = A_VHI + NP * 128;    // 79872
constexpr int A_KV_END = A_VLO + NP * 128; // 106496
// Q overlay (within the KV region): hi at 0, lo at 28672.
constexpr int A_QHI = 0;
constexpr int A_QLO = 28672;               // MP*128
constexpr int A_TB  = A_KV_END;            // table after KV region
constexpr int SMEM_ATT = A_TB + 729 * 4 + 28;  // ~107 KB -> 2 CTAs/SM

// Scratch (device globals; runtime allocation is forbidden; BSS is zero-init,
// so padded rows of q/k/v read as zeros).
__device__ __nv_bfloat16 g_qhi[(long)NWIN * NHD * MP * HD];
__device__ __nv_bfloat16 g_qlo[(long)NWIN * NHD * MP * HD];
__device__ __nv_bfloat16 g_khi[(long)NWIN * NHD * NP * HD];
__device__ __nv_bfloat16 g_klo[(long)NWIN * NHD * NP * HD];
__device__ __nv_bfloat16 g_vhi[(long)NWIN * NHD * NP * HD];
__device__ __nv_bfloat16 g_vlo[(long)NWIN * NHD * NP * HD];
__device__ __nv_bfloat16 g_xhi[(long)M1 * CDIM];
__device__ __nv_bfloat16 g_xlo[(long)M1 * CDIM];
__device__ __nv_bfloat16 g_whi[(long)QKVN * CDIM];
__device__ __nv_bfloat16 g_wlo[(long)QKVN * CDIM];
__device__ __nv_bfloat16 g_pwhi[(long)CDIM * CDIM];
__device__ __nv_bfloat16 g_pwlo[(long)CDIM * CDIM];
__device__ __nv_bfloat16 g_ahi[(long)M1 * CDIM];
__device__ __nv_bfloat16 g_alo[(long)M1 * CDIM];

// ---------------------------------------------------------------------------
// PTX helpers (base-target instructions only; tcgen05 is rejected by ptxas
// on the harness's compute_103 virtual target).
// ---------------------------------------------------------------------------
__device__ __forceinline__ uint32_t smem_u32(const void* p) {
    uint32_t a;
    asm("{ .reg .u64 t; cvta.to.shared.u64 t, %1; cvt.u32.u64 %0, t; }"
        : "=r"(a) : "l"(p));
    return a;
}
__device__ __forceinline__ void cp16(uint32_t dst, const void* src) {
    asm volatile("cp.async.cg.shared.global [%0], [%1], 16;"
                 :: "r"(dst), "l"(src));
}
__device__ __forceinline__ void cp_commit() {
    asm volatile("cp.async.commit_group;");
}
__device__ __forceinline__ void cp_wait0() {
    asm volatile("cp.async.wait_group 0;" ::: "memory");
}
__device__ __forceinline__ void mbar_init(uint32_t a, uint32_t cnt) {
    asm volatile("mbarrier.init.shared.b64 [%0], %1;" :: "r"(a), "r"(cnt) : "memory");
}
__device__ __forceinline__ void mbar_arrive(uint32_t a) {
    asm volatile("mbarrier.arrive.shared.b64 _, [%0];" :: "r"(a) : "memory");
}
// .noinc is load-bearing: the async completion's arrival must count against
// the init()-time expected count (R11/R12 hang root cause).
__device__ __forceinline__ void cp_arrive(uint32_t a) {
    asm volatile("cp.async.mbarrier.arrive.noinc.shared.b64 [%0];" :: "r"(a) : "memory");
}
__device__ __forceinline__ void mbar_wait(uint32_t a, uint32_t par) {
    asm volatile(
        "{\n\t.reg .pred P1;\n\t"
        "WL_%=:\n\t"
        "mbarrier.try_wait.parity.acquire.cta.shared::cta.b64 P1, [%0], %1, 0x989680;\n\t"
        "@P1 bra.uni WD_%=;\n\t"
        "bra.uni WL_%=;\n\t"
        "WD_%=:\n\t}"
        :: "r"(a), "r"(par) : "memory");
}
__device__ __forceinline__ void ldsm4(uint32_t* r, uint32_t addr) {
    asm volatile("ldmatrix.sync.aligned.m8n8.x4.shared.b16 {%0,%1,%2,%3}, [%4];"
                 : "=r"(r[0]), "=r"(r[1]), "=r"(r[2]), "=r"(r[3]) : "r"(addr));
}
__device__ __forceinline__ void ldsm4t(uint32_t* r, uint32_t addr) {
    asm volatile("ldmatrix.sync.aligned.m8n8.x4.trans.shared.b16 {%0,%1,%2,%3}, [%4];"
                 : "=r"(r[0]), "=r"(r[1]), "=r"(r[2]), "=r"(r[3]) : "r"(addr));
}
__device__ __forceinline__ void mma16816(float* d, const uint32_t* a,
                                         uint32_t b0, uint32_t b1) {
    asm volatile(
        "mma.sync.aligned.m16n8k16.row.col.f32.bf16.bf16.f32 "
        "{%0,%1,%2,%3}, {%4,%5,%6,%7}, {%8,%9}, {%0,%1,%2,%3};"
        : "+f"(d[0]), "+f"(d[1]), "+f"(d[2]), "+f"(d[3])
        : "r"(a[0]), "r"(a[1]), "r"(a[2]), "r"(a[3]), "r"(b0), "r"(b1));
}

// 2 floats -> bf16x2 hi + bf16x2 lo words.
__device__ __forceinline__ void split2(float x, float y, uint32_t& h, uint32_t& l) {
    __nv_bfloat162 hh = __floats2bfloat162_rn(x, y);
    float2 f = __bfloat1622float2(hh);
    __nv_bfloat162 ll = __floats2bfloat162_rn(x - f.x, y - f.y);
    h = *(uint32_t*)&hh; l = *(uint32_t*)&ll;
}
// 4 floats -> bf16 hi (8B) + bf16 lo (8B).
__device__ __forceinline__ void split4(float4 v, uint2& hi, uint2& lo) {
    split2(v.x, v.y, hi.x, lo.x);
    split2(v.z, v.w, hi.y, lo.y);
}

// ---------------------------------------------------------------------------
// Kernel 0: fp32 -> bf16 hi/lo conversion (elementwise).
// ---------------------------------------------------------------------------
__global__ __launch_bounds__(256) void k_cvt(const float* __restrict__ src,
                                            __nv_bfloat16* __restrict__ hi,
                                            __nv_bfloat16* __restrict__ lo,
                                            long n4)
{
    const long i = (long)blockIdx.x * blockDim.x + threadIdx.x;
    if (i >= n4) return;
    float4 v = *(const float4*)(src + i * 4);
    uint2 h, l;
    split4(v, h, l);
    *(uint2*)(hi + i * 4) = h;
    *(uint2*)(lo + i * 4) = l;
}

// ---------------------------------------------------------------------------
// Shared bf16 GEMM mainloop (R13 exact): CTA 128x128, warp 32x64, 3 stages,
// mbarrier-gated pipeline.
// ---------------------------------------------------------------------------
__device__ __forceinline__ void gemm_main(uint32_t smb,
                                          const __nv_bfloat16* aHiR,
                                          const __nv_bfloat16* aLoR,
                                          const __nv_bfloat16* bHiR,
                                          const __nv_bfloat16* bLoR,
                                          float acc[2][8][4]) {
    const int tid = threadIdx.x;
    const int lane = tid & 31, wid = tid >> 5;
    const int srow = tid >> 1, shalf = tid & 1;
    const int bswz = (srow >> 1) & 3;

    const uint32_t FILL = smb + MB_OFF;        // 3 x 8B
    const uint32_t FREE = smb + MB_OFF + 24;   // 3 x 8B
    if (tid == 0) {
#pragma unroll
        for (int s = 0; s < 3; s++) {
            mbar_init(FILL + 8 * s, 256);
            mbar_init(FREE + 8 * s, 8);
        }
    }
    __syncthreads();

    const uint32_t d0 = srow * 64 + (((shalf * 2 + 0) ^ bswz) * 16);
    const uint32_t d1 = srow * 64 + (((shalf * 2 + 1) ^ bswz) * 16);
    const int e0 = (shalf * 2 + 0) * 8;
    const int e1 = (shalf * 2 + 1) * 8;

    auto issue = [&](int c) {
        const int t = c % 3;
        const uint32_t st = smb + t * STG_B;
        const int kb = c * KCH;
        cp16(st + T_AHI + d0, aHiR + kb + e0);
        cp16(st + T_AHI + d1, aHiR + kb + e1);
        cp16(st + T_ALO + d0, aLoR + kb + e0);
        cp16(st + T_ALO + d1, aLoR + kb + e1);
        cp16(st + T_BHI + d0, bHiR + kb + e0);
        cp16(st + T_BHI + d1, bHiR + kb + e1);
        cp16(st + T_BLO + d0, bLoR + kb + e0);
        cp16(st + T_BLO + d1, bLoR + kb + e1);
        cp_arrive(FILL + 8 * t);
    };

    const int m_base = (wid & 3) * 32;
    const int n_base = (wid >> 2) * 64;
    const int lr = lane & 15, lh = lane >> 4;
    const int rA = m_base + lr;
    const int rB = n_base + lr;
    const uint32_t swA = (rA >> 1) & 3;
    const uint32_t swB = (rB >> 1) & 3;
    const uint32_t paS[2] = {((0 + lh) ^ swA) * 16, ((2 + lh) ^ swA) * 16};
    const uint32_t pbS[2] = {((0 + lh) ^ swB) * 16, ((2 + lh) ^ swB) * 16};
    const uint32_t rA64 = rA * 64, rB64 = rB * 64;

    issue(0);
    issue(1);
    for (int c = 0; c < NCH; c++) {
        const int s = c % 3;
        const int u = c / 3;
        mbar_wait(FILL + 8 * s, (uint32_t)(u & 1));

        const uint32_t st = smb + s * STG_B;
        const uint32_t aHi = st + T_AHI + rA64;
        const uint32_t aLo = st + T_ALO + rA64;
        const uint32_t bHi = st + T_BHI + rB64;
        const uint32_t bLo = st + T_BLO + rB64;

#pragma unroll
        for (int ks = 0; ks < 2; ks++) {
            const uint32_t pa = paS[ks], pb = pbS[ks];
            uint32_t ah[2][4], al[2][4];
            ldsm4(ah[0], aHi + pa); ldsm4(ah[1], aHi + 1024 + pa);
            ldsm4(al[0], aLo + pa); ldsm4(al[1], aLo + 1024 + pa);
            uint32_t bh[4][4], bl[4][4];
#pragma unroll
            for (int nfp = 0; nfp < 4; nfp++) {
                ldsm4(bh[nfp], bHi + nfp * 1024 + pb);
                ldsm4(bl[nfp], bLo + nfp * 1024 + pb);
            }
            if (ks == 1) {
                // All ldsm reads of this stage are done: free it, then
                // (after all warps freed it) refill with chunk c+2.
                if (lane == 0) mbar_arrive(FREE + 8 * s);
                if (c + 2 < NCH) {
                    const int t = (c + 2) % 3;
                    const int v = (c + 2) / 3;
                    if (v > 0) mbar_wait(FREE + 8 * t, (uint32_t)((v - 1) & 1));
                    issue(c + 2);
                }
            }
#pragma unroll
            for (int nfp = 0; nfp < 4; nfp++)
#pragma unroll
                for (int mf = 0; mf < 2; mf++)
#pragma unroll
                    for (int q = 0; q < 2; q++) {
                        float* d = acc[mf][nfp * 2 + q];
                        mma16816(d, ah[mf], bh[nfp][q], bh[nfp][q + 2]); // hi*hi
                        mma16816(d, ah[mf], bl[nfp][q], bl[nfp][q + 2]); // hi*lo
                        mma16816(d, al[mf], bh[nfp][q], bh[nfp][q + 2]); // lo*hi
                    }
        }
    }
}

// ---------------------------------------------------------------------------
// Kernel 1: fused window-partition + QKV GEMM; epilogue writes q/k/v as
// bf16 hi/lo into padded per-(window,head) layouts for the mma attention.
// ---------------------------------------------------------------------------
__global__ __launch_bounds__(256, 2) void k_qkv_mma(
    const float* __restrict__ qb, const float* __restrict__ vb)
{
    extern __shared__ char sm[];
    const uint32_t smb = smem_u32(sm);
    const int tid = threadIdx.x;
    const int lane = tid & 31, wid = tid >> 5;
    const int bn = blockIdx.x, bm = blockIdx.y;
    const int m0 = bm * 128, n0 = bn * 128;

    long aoff;
    {
        const int srow = tid >> 1;
        const int am = m0 + srow;
        const int wwin = am / NT;
        const int nn = am - wwin * NT;
        const int bimg = wwin >> 4, wi = wwin & 15;
        const int rr = (wi >> 2) * WSZ + nn / WSZ;
        const int cc = (wi & 3) * WSZ + nn % WSZ;
        aoff = ((long)bimg * 3136 + (long)rr * 56 + cc) * CDIM;
    }
    const long boff = (long)(n0 + (tid >> 1)) * CDIM;

    float acc[2][8][4];
#pragma unroll
    for (int a = 0; a < 2; a++)
#pragma unroll
        for (int b = 0; b < 8; b++)
#pragma unroll
            for (int c = 0; c < 4; c++) acc[a][b][c] = 0.f;

    gemm_main(smb, g_xhi + aoff, g_xlo + aoff, g_whi + boff, g_wlo + boff, acc);

    // Epilogue: split-bf16 scatter into padded q/k/v.
    const int m_base = (wid & 3) * 32, n_base = (wid >> 2) * 64;
    const int qrow = lane >> 2, qcol = (lane & 3) * 2;
    const int part = n0 / CDIM;              // 0:q 1:k 2:v
    const int jrbase = n0 - part * CDIM + n_base;
    const int hh = jrbase >> 6;
    __nv_bfloat16* dhi = (part == 0) ? g_qhi : (part == 1) ? g_khi : g_vhi;
    __nv_bfloat16* dlo = (part == 0) ? g_qlo : (part == 1) ? g_klo : g_vlo;
    const int rstr = (part == 0) ? MP : NP;

#pragma unroll
    for (int mf = 0; mf < 2; mf++)
#pragma unroll
        for (int half = 0; half < 2; half++) {
            const int rl = m_base + mf * 16 + half * 8 + qrow;
            const int m = m0 + rl;
            const int w2 = m / NT, n2 = m - w2 * NT;
            const long rb = (((long)w2 * NHD + hh) * rstr + n2) * HD;
#pragma unroll
            for (int nf = 0; nf < 8; nf++) {
                const int dd = nf * 8 + qcol;
                float vx = acc[mf][nf][half * 2 + 0];
                float vy = acc[mf][nf][half * 2 + 1];
                const int jr = jrbase + dd;
                if (part == 0) {
                    vx = (vx + qb[jr]) * 0.125f;
                    vy = (vy + qb[jr + 1]) * 0.125f;
                } else if (part == 2) {
                    vx += vb[jr]; vy += vb[jr + 1];
                }
                uint32_t h, l;
                split2(vx, vy, h, l);
                *(uint32_t*)(dhi + rb + dd) = h;
                *(uint32_t*)(dlo + rb + dd) = l;
            }
        }
}

// ---------------------------------------------------------------------------
// Kernel 2: windowed attention via split-bf16 mma.sync.
// Two-phase smem: Q staged -> fragments -> region overwritten with K/V.
// Peak smem ~107 KB -> 2 CTAs/SM (14 warps) for cross-CTA latency cover.
// ---------------------------------------------------------------------------
__global__ __launch_bounds__(224, 2) void k_attn_mma(const float* __restrict__ table)
{
    extern __shared__ char sm[];
    const uint32_t smb = smem_u32(sm);
    float* tbs = (float*)(sm + A_TB);
    const int w = blockIdx.x, h = blockIdx.y;
    const int tid = threadIdx.x;
    const int lane = tid & 31, wid = tid >> 5;   // wid 0..6
    const int lr = lane & 15, lh = lane >> 4;

    // --- phase 1: stage Q hi/lo, extract fragments ---
    {
        const long qb = ((long)w * NHD + h) * MP * HD;
        for (int idx = tid; idx < MP * 8; idx += 224) {
            const int row = idx >> 3, c = idx & 7;
            const uint32_t off = row * 128 + ((c ^ (row & 7)) << 4);
            const long go = qb + row * 64 + c * 8;
            cp16(smb + A_QHI + off, g_qhi + go);
            cp16(smb + A_QLO + off, g_qlo + go);
        }
        cp_commit();
        cp_wait0();
    }
    __syncthreads();

    uint32_t qfh[2][4][4], qfl[2][4][4];
#pragma unroll
    for (int mf = 0; mf < 2; mf++)
#pragma unroll
        for (int s = 0; s < 4; s++) {
            const int row = wid * 32 + mf * 16 + lr;
            const uint32_t off = row * 128 + (((2 * s + lh) ^ (row & 7)) << 4);
            ldsm4(qfh[mf][s], smb + A_QHI + off);
            ldsm4(qfl[mf][s], smb + A_QLO + off);
        }
    __syncthreads();   // everyone done reading Q before overwrite

    // --- phase 2: K/V hi/lo into the same region + bias table ---
    {
        const long kb = ((long)w * NHD + h) * NP * HD;
        for (int idx = tid; idx < NP * 8; idx += 224) {
            const int row = idx >> 3, c = idx & 7;
            const uint32_t off = row * 128 + ((c ^ (row & 7)) << 4);
            const long go = kb + row * 64 + c * 8;
            cp16(smb + A_KHI + off, g_khi + go);
            cp16(smb + A_KLO + off, g_klo + go);
            cp16(smb + A_VHI + off, g_vhi + go);
            cp16(smb + A_VLO + off, g_vlo + go);
        }
        cp_commit();
        for (int t = tid; t < 729; t += 224) tbs[t] = table[t * NHD + h];
        cp_wait0();
    }
    __syncthreads();

    // --- per-thread row info (4 rows: [mf][rh]) ---
    int rbias[2][2];
    bool rok[2][2];
    const int g = lane >> 2;
#pragma unroll
    for (int mf = 0; mf < 2; mf++)
#pragma unroll
        for (int rh = 0; rh < 2; rh++) {
            const int r = wid * 32 + mf * 16 + rh * 8 + g;
            rok[mf][rh] = (r < NT);
            const int iy = r / WSZ, ix = r - (r / WSZ) * WSZ;
            rbias[mf][rh] = iy * 27 + ix + 13 * 28;
        }

    float mM[2][2], lL[2][2];
    float o[2][8][4];
#pragma unroll
    for (int mf = 0; mf < 2; mf++)
#pragma unroll
        for (int rh = 0; rh < 2; rh++) { mM[mf][rh] = -1e30f; lL[mf][rh] = 0.f; }
#pragma unroll
    for (int a = 0; a < 2; a++)
#pragma unroll
        for (int b = 0; b < 8; b++)
#pragma unroll
            for (int c = 0; c < 4; c++) o[a][b][c] = 0.f;

    const int cbase = 2 * (lane & 3);

    for (int it = 0; it < 13; it++) {
        // K fragments for this 16-key tile.
        uint32_t kfh[4][4], kfl[4][4];
#pragma unroll
        for (int s = 0; s < 4; s++) {
            const int row = it * 16 + lr;
            const uint32_t off = row * 128 + (((2 * s + lh) ^ (row & 7)) << 4);
            ldsm4(kfh[s], smb + A_KHI + off);
            ldsm4(kfl[s], smb + A_KLO + off);
        }
        // S = Q K^T (3-term split), fp32 accum.
        float sc[2][2][4];
#pragma unroll
        for (int mf = 0; mf < 2; mf++)
#pragma unroll
            for (int q = 0; q < 2; q++)
#pragma unroll
                for (int e = 0; e < 4; e++) sc[mf][q][e] = 0.f;
#pragma unroll
        for (int s = 0; s < 4; s++)
#pragma unroll
            for (int q = 0; q < 2; q++)
#pragma unroll
                for (int mf = 0; mf < 2; mf++) {
                    float* d = sc[mf][q];
                    mma16816(d, qfh[mf][s], kfh[s][q], kfh[s][q + 2]);
                    mma16816(d, qfh[mf][s], kfl[s][q], kfl[s][q + 2]);
                    mma16816(d, qfl[mf][s], kfh[s][q], kfh[s][q + 2]);
                }

        // Bias gather + mask.
        int cidx[2][2];
        bool cok[2][2];
#pragma unroll
        for (int q = 0; q < 2; q++)
#pragma unroll
            for (int e1 = 0; e1 < 2; e1++) {
                const int c = it * 16 + q * 8 + cbase + e1;
                cok[q][e1] = (c < NT);
                const int jy = c / WSZ;
                cidx[q][e1] = jy * 27 + (c - jy * WSZ);
            }
#pragma unroll
        for (int mf = 0; mf < 2; mf++)
#pragma unroll
            for (int q = 0; q < 2; q++)
#pragma unroll
                for (int e = 0; e < 4; e++) {
                    const int rh = e >> 1, e1 = e & 1;
                    if (!cok[q][e1]) sc[mf][q][e] = -1e30f;
                    else if (rok[mf][rh])
                        sc[mf][q][e] += tbs[rbias[mf][rh] - cidx[q][e1]];
                }

        // Online softmax per row group.
#pragma unroll
        for (int mf = 0; mf < 2; mf++)
#pragma unroll
            for (int rh = 0; rh < 2; rh++) {
                float vmax = fmaxf(fmaxf(sc[mf][0][2 * rh], sc[mf][0][2 * rh + 1]),
                                   fmaxf(sc[mf][1][2 * rh], sc[mf][1][2 * rh + 1]));
                vmax = fmaxf(vmax, __shfl_xor_sync(0xffffffffu, vmax, 1));
                vmax = fmaxf(vmax, __shfl_xor_sync(0xffffffffu, vmax, 2));
                const float mn = fmaxf(mM[mf][rh], vmax);
                const float corr = __expf(mM[mf][rh] - mn);
                mM[mf][rh] = mn;
                float rs = 0.f;
#pragma unroll
                for (int q = 0; q < 2; q++)
#pragma unroll
                    for (int e1 = 0; e1 < 2; e1++) {
                        const float p = __expf(sc[mf][q][2 * rh + e1] - mn);
                        sc[mf][q][2 * rh + e1] = p;
                        rs += p;
                    }
                rs += __shfl_xor_sync(0xffffffffu, rs, 1);
                rs += __shfl_xor_sync(0xffffffffu, rs, 2);
                lL[mf][rh] = lL[mf][rh] * corr + rs;
#pragma unroll
                for (int n = 0; n < 8; n++) {
                    o[mf][n][2 * rh + 0] *= corr;
                    o[mf][n][2 * rh + 1] *= corr;
                }
            }

        // P -> A-fragments (hi/lo).  C-frag(m16n16) == A-frag(m16k16).
        uint32_t pfh[2][4], pfl[2][4];
#pragma unroll
        for (int mf = 0; mf < 2; mf++) {
            split2(sc[mf][0][0], sc[mf][0][1], pfh[mf][0], pfl[mf][0]);
            split2(sc[mf][0][2], sc[mf][0][3], pfh[mf][1], pfl[mf][1]);
            split2(sc[mf][1][0], sc[mf][1][1], pfh[mf][2], pfl[mf][2]);
            split2(sc[mf][1][2], sc[mf][1][3], pfh[mf][3], pfl[mf][3]);
        }

        // O += P V (V via ldmatrix.trans; 3-term split).
#pragma unroll
        for (int gg = 0; gg < 4; gg++) {
            const int row = it * 16 + lr;
            const uint32_t off = row * 128 + (((2 * gg + lh) ^ (row & 7)) << 4);
            uint32_t vfh[4], vfl[4];
            ldsm4t(vfh, smb + A_VHI + off);
            ldsm4t(vfl, smb + A_VLO + off);
#pragma unroll
            for (int q = 0; q < 2; q++)
#pragma unroll
                for (int mf = 0; mf < 2; mf++) {
                    float* d = o[mf][gg * 2 + q];
                    mma16816(d, pfh[mf], vfh[2 * q], vfh[2 * q + 1]);
                    mma16816(d, pfh[mf], vfl[2 * q], vfl[2 * q + 1]);
                    mma16816(d, pfl[mf], vfh[2 * q], vfh[2 * q + 1]);
                }
        }
    }

    // Epilogue: divide by l, window-reverse, emit bf16 hi/lo for proj GEMM.
    const int bimg = w >> 4, wi = w & 15;
#pragma unroll
    for (int mf = 0; mf < 2; mf++)
#pragma unroll
        for (int rh = 0; rh < 2; rh++) {
            if (!rok[mf][rh]) continue;
            const int r = wid * 32 + mf * 16 + rh * 8 + g;
            const int iy = r / WSZ, ix = r - (r / WSZ) * WSZ;
            const int rr = (wi >> 2) * WSZ + iy;
            const int cc = (wi & 3) * WSZ + ix;
            const long ob = ((long)bimg * 3136 + (long)rr * 56 + cc) * CDIM + h * HD;
            const float inv = 1.f / lL[mf][rh];
#pragma unroll
            for (int n = 0; n < 8; n++) {
                const int col = n * 8 + cbase;
                uint32_t hh, ll;
                split2(o[mf][n][2 * rh] * inv, o[mf][n][2 * rh + 1] * inv, hh, ll);
                *(uint32_t*)(g_ahi + ob + col) = hh;
                *(uint32_t*)(g_alo + ob + col) = ll;
            }
        }
}

// ---------------------------------------------------------------------------
// Kernel 3: output projection GEMM (bf16 inputs from g_ahi/lo, g_pwhi/lo)
// ---------------------------------------------------------------------------
__global__ __launch_bounds__(256, 2) void k_proj_mma(
    const float* __restrict__ pb, float* __restrict__ out)
{
    extern __shared__ char sm[];
    const uint32_t smb = smem_u32(sm);
    const int tid = threadIdx.x;
    const int lane = tid & 31, wid = tid >> 5;
    const int bn = blockIdx.x, bm = blockIdx.y;
    const int m0 = bm * 128, n0 = bn * 128;

    const long aoff = (long)(m0 + (tid >> 1)) * CDIM;
    const long boff = (long)(n0 + (tid >> 1)) * CDIM;

    float acc[2][8][4];
#pragma unroll
    for (int a = 0; a < 2; a++)
#pragma unroll
        for (int b = 0; b < 8; b++)
#pragma unroll
            for (int c = 0; c < 4; c++) acc[a][b][c] = 0.f;

    gemm_main(smb, g_ahi + aoff, g_alo + aoff, g_pwhi + boff, g_pwlo + boff, acc);

    const int m_base = (wid & 3) * 32, n_base = (wid >> 2) * 64;
    const int qrow = lane >> 2, qcol = (lane & 3) * 2;

#pragma unroll
    for (int mf = 0; mf < 2; mf++)
#pragma unroll
        for (int half = 0; half < 2; half++) {
            const int rl = m_base + mf * 16 + half * 8 + qrow;
            const int m = m0 + rl;
            float* rp = out + (long)m * CDIM + n0 + n_base;
#pragma unroll
            for (int nf = 0; nf < 8; nf++) {
                const int dd = nf * 8 + qcol;
                const float2 bias = *(const float2*)(pb + n0 + n_base + dd);
                *(float2*)(rp + dd) = make_float2(
                    acc[mf][nf][half * 2 + 0] + bias.x,
                    acc[mf][nf][half * 2 + 1] + bias.y);
            }
        }
}

// ---------------------------------------------------------------------------
extern "C" void kernel_launch(void* const* d_in, const int* in_sizes, int n_in,
                              void* d_out, int out_size)
{
    const float* x    = (const float*)d_in[0];
    const float* qkvw = (const float*)d_in[1];
    const float* qb   = (const float*)d_in[2];
    const float* vb   = (const float*)d_in[3];
    const float* tbl  = (const float*)d_in[4];
    const float* pw   = (const float*)d_in[5];
    const float* pb   = (const float*)d_in[6];
    float* out = (float*)d_out;

    cudaFuncSetAttribute(k_qkv_mma,
                         cudaFuncAttributeMaxDynamicSharedMemorySize, SMEM_TOT);
    cudaFuncSetAttribute(k_proj_mma,
                         cudaFuncAttributeMaxDynamicSharedMemorySize, SMEM_TOT);
    cudaFuncSetAttribute(k_attn_mma,
                         cudaFuncAttributeMaxDynamicSharedMemorySize, SMEM_ATT);

    __nv_bfloat16 *xhi, *xlo, *whi, *wlo, *pwhi, *pwlo;
    cudaGetSymbolAddress((void**)&xhi, g_xhi);
    cudaGetSymbolAddress((void**)&xlo, g_xlo);
    cudaGetSymbolAddress((void**)&whi, g_whi);
    cudaGetSymbolAddress((void**)&wlo, g_wlo);
    cudaGetSymbolAddress((void**)&pwhi, g_pwhi);
    cudaGetSymbolAddress((void**)&pwlo, g_pwlo);

    // Pre-convert fp32 operands to bf16 hi/lo.
    {
        const long n4x = (long)M1 * CDIM / 4;
        k_cvt<<<(unsigned)((n4x + 255) / 256), 256>>>(x, xhi, xlo, n4x);
        const long n4w = (long)QKVN * CDIM / 4;
        k_cvt<<<(unsigned)((n4w + 255) / 256), 256>>>(qkvw, whi, wlo, n4w);
        const long n4p = (long)CDIM * CDIM / 4;
        k_cvt<<<(unsigned)((n4p + 255) / 256), 256>>>(pw, pwhi, pwlo, n4p);
    }

    dim3 g1(QKVN / 128, M1 / 128);   // (18, 392)
    k_qkv_mma<<<g1, 256, SMEM_TOT>>>(qb, vb);

    dim3 g2(NWIN, NHD);              // (256, 12)
    k_attn_mma<<<g2, 224, SMEM_ATT>>>(tbl);

    dim3 g3(CDIM / 128, M1 / 128);   // (6, 392)
    k_proj_mma<<<g3, 256, SMEM_TOT>>>(pb, out);
}

// round 15
// speedup vs baseline: 1.3933x; 1.3933x over previous
#include <cuda_runtime.h>
#include <cuda_bf16.h>
#include <cstdint>

// Problem constants.
constexpr int CDIM = 768;
constexpr int NHD  = 12;
constexpr int HD   = 64;
constexpr int WSZ  = 14;
constexpr int NT   = WSZ * WSZ;        // 196
constexpr int NWIN = 256;
constexpr int M1   = NWIN * NT;        // 50176
constexpr int QKVN = 3 * CDIM;         // 2304

// Attention padded dims (mma tiles of 16).
constexpr int MP = 224;                // query rows padded (14 x 16)
constexpr int NP = 208;                // key rows padded (13 x 16)

// GEMM tiling (tf32): CTA 128x128, K-chunk 32 fp32, 8 warps (4Mx2N), 3 stages.
constexpr int KCH = 32;
constexpr int NCH = CDIM / KCH;        // 24
constexpr int T_A32 = 0;               // A tile: 128 rows x 128B = 16 KB
constexpr int T_B32 = 16384;           // B tile: 16 KB
constexpr int STG_B = 32768;
constexpr int MB_OFF = 3 * STG_B;      // 6 mbarriers after the stages
constexpr int SMEM_TOT = MB_OFF + 64;  // 96 KB + 64

// Attention smem layout (R13 exact; bf16 split path).
constexpr int A_QHI = 0;
constexpr int A_QLO = A_QHI + MP * 128;    // 28672
constexpr int A_KHI = A_QLO + MP * 128;    // 57344
constexpr int A_KLO = A_KHI + NP * 128;    // 83968
constexpr int A_VHI = A_KLO + NP * 128;    // 110592
constexpr int A_VLO = A_VHI + NP * 128;    // 137216
constexpr int A_TB  = A_VLO + NP * 128;    // 163840
constexpr int SMEM_ATT = A_TB + 729 * 4 + 28;  // ~163 KB

// Scratch (device globals; runtime allocation is forbidden; BSS is zero-init,
// so padded rows of q/k/v read as zeros).
__device__ __nv_bfloat16 g_qhi[(long)NWIN * NHD * MP * HD];
__device__ __nv_bfloat16 g_qlo[(long)NWIN * NHD * MP * HD];
__device__ __nv_bfloat16 g_khi[(long)NWIN * NHD * NP * HD];
__device__ __nv_bfloat16 g_klo[(long)NWIN * NHD * NP * HD];
__device__ __nv_bfloat16 g_vhi[(long)NWIN * NHD * NP * HD];
__device__ __nv_bfloat16 g_vlo[(long)NWIN * NHD * NP * HD];
__device__ float g_x32[(long)M1 * CDIM];    // tf32-rounded inputs
__device__ float g_w32[(long)QKVN * CDIM];
__device__ float g_pw32[(long)CDIM * CDIM];
__device__ float g_a32[(long)M1 * CDIM];    // attention output (tf32-rounded)

// ---------------------------------------------------------------------------
// PTX helpers (base-target instructions only; tcgen05 is rejected by ptxas
// on the harness's compute_103 virtual target).
// ---------------------------------------------------------------------------
__device__ __forceinline__ uint32_t smem_u32(const void* p) {
    uint32_t a;
    asm("{ .reg .u64 t; cvta.to.shared.u64 t, %1; cvt.u32.u64 %0, t; }"
        : "=r"(a) : "l"(p));
    return a;
}
__device__ __forceinline__ void cp16(uint32_t dst, const void* src) {
    asm volatile("cp.async.cg.shared.global [%0], [%1], 16;"
                 :: "r"(dst), "l"(src));
}
__device__ __forceinline__ void cp_commit() {
    asm volatile("cp.async.commit_group;");
}
__device__ __forceinline__ void cp_wait0() {
    asm volatile("cp.async.wait_group 0;" ::: "memory");
}
__device__ __forceinline__ void mbar_init(uint32_t a, uint32_t cnt) {
    asm volatile("mbarrier.init.shared.b64 [%0], %1;" :: "r"(a), "r"(cnt) : "memory");
}
__device__ __forceinline__ void mbar_arrive(uint32_t a) {
    asm volatile("mbarrier.arrive.shared.b64 _, [%0];" :: "r"(a) : "memory");
}
// .noinc is load-bearing: the async completion's arrival must count against
// the init()-time expected count (R11/R12 hang root cause).
__device__ __forceinline__ void cp_arrive(uint32_t a) {
    asm volatile("cp.async.mbarrier.arrive.noinc.shared.b64 [%0];" :: "r"(a) : "memory");
}
__device__ __forceinline__ void mbar_wait(uint32_t a, uint32_t par) {
    asm volatile(
        "{\n\t.reg .pred P1;\n\t"
        "WL_%=:\n\t"
        "mbarrier.try_wait.parity.acquire.cta.shared::cta.b64 P1, [%0], %1, 0x989680;\n\t"
        "@P1 bra.uni WD_%=;\n\t"
        "bra.uni WL_%=;\n\t"
        "WD_%=:\n\t}"
        :: "r"(a), "r"(par) : "memory");
}
__device__ __forceinline__ void ldsm4(uint32_t* r, uint32_t addr) {
    asm volatile("ldmatrix.sync.aligned.m8n8.x4.shared.b16 {%0,%1,%2,%3}, [%4];"
                 : "=r"(r[0]), "=r"(r[1]), "=r"(r[2]), "=r"(r[3]) : "r"(addr));
}
__device__ __forceinline__ void ldsm4t(uint32_t* r, uint32_t addr) {
    asm volatile("ldmatrix.sync.aligned.m8n8.x4.trans.shared.b16 {%0,%1,%2,%3}, [%4];"
                 : "=r"(r[0]), "=r"(r[1]), "=r"(r[2]), "=r"(r[3]) : "r"(addr));
}
__device__ __forceinline__ void mma16816(float* d, const uint32_t* a,
                                         uint32_t b0, uint32_t b1) {
    asm volatile(
        "mma.sync.aligned.m16n8k16.row.col.f32.bf16.bf16.f32 "
        "{%0,%1,%2,%3}, {%4,%5,%6,%7}, {%8,%9}, {%0,%1,%2,%3};"
        : "+f"(d[0]), "+f"(d[1]), "+f"(d[2]), "+f"(d[3])
        : "r"(a[0]), "r"(a[1]), "r"(a[2]), "r"(a[3]), "r"(b0), "r"(b1));
}
__device__ __forceinline__ void mma_tf32(float* d, const uint32_t* a,
                                         uint32_t b0, uint32_t b1) {
    asm volatile(
        "mma.sync.aligned.m16n8k8.row.col.f32.tf32.tf32.f32 "
        "{%0,%1,%2,%3}, {%4,%5,%6,%7}, {%8,%9}, {%0,%1,%2,%3};"
        : "+f"(d[0]), "+f"(d[1]), "+f"(d[2]), "+f"(d[3])
        : "r"(a[0]), "r"(a[1]), "r"(a[2]), "r"(a[3]), "r"(b0), "r"(b1));
}

// Round-to-nearest tf32 (keeps fp32 container). .rna is load-bearing: raw
// truncation inside mma would add a coherent ~2^-10 bias over K=768.
__device__ __forceinline__ float tf32r(float x) {
    uint32_t u;
    asm("cvt.rna.tf32.f32 %0, %1;" : "=r"(u) : "f"(x));
    return __uint_as_float(u);
}

// 2 floats -> bf16x2 hi + bf16x2 lo words (attention q/k/v path).
__device__ __forceinline__ void split2(float x, float y, uint32_t& h, uint32_t& l) {
    __nv_bfloat162 hh = __floats2bfloat162_rn(x, y);
    float2 f = __bfloat1622float2(hh);
    __nv_bfloat162 ll = __floats2bfloat162_rn(x - f.x, y - f.y);
    h = *(uint32_t*)&hh; l = *(uint32_t*)&ll;
}

// ---------------------------------------------------------------------------
// Kernel 0: fp32 -> tf32-rounded fp32 (elementwise).
// ---------------------------------------------------------------------------
__global__ __launch_bounds__(256) void k_cvt32(const float* __restrict__ src,
                                              float* __restrict__ dst, long n4)
{
    const long i = (long)blockIdx.x * blockDim.x + threadIdx.x;
    if (i >= n4) return;
    float4 v = *(const float4*)(src + i * 4);
    v.x = tf32r(v.x); v.y = tf32r(v.y); v.z = tf32r(v.z); v.w = tf32r(v.w);
    *(float4*)(dst + i * 4) = v;
}

// ---------------------------------------------------------------------------
// Shared tf32 GEMM mainloop: CTA 128x128, warp 32x64, K-chunk 32 fp32,
// 3 stages, mbarrier-gated pipeline (R13 protocol). Per chunk: 4 k-steps of 8,
// per k-step per warp: 2 A-ldsm.x4 + 4 B-ldsm.x4 + 16 mma.tf32.
// ---------------------------------------------------------------------------
__device__ __forceinline__ void gemm_main(uint32_t smb,
                                          const float* aR, const float* bR,
                                          float acc[2][8][4]) {
    const int tid = threadIdx.x;
    const int lane = tid & 31, wid = tid >> 5;
    const int srow = tid >> 1, shalf = tid & 1;
    const int sswz = srow & 7;

    const uint32_t FILL = smb + MB_OFF;        // 3 x 8B
    const uint32_t FREE = smb + MB_OFF + 24;   // 3 x 8B
    if (tid == 0) {
#pragma unroll
        for (int s = 0; s < 3; s++) {
            mbar_init(FILL + 8 * s, 256);
            mbar_init(FREE + 8 * s, 8);
        }
    }
    __syncthreads();

    // cp.async destination offsets (4 x 16B per tile per thread).
    uint32_t dof[4];
#pragma unroll
    for (int j = 0; j < 4; j++)
        dof[j] = srow * 128 + (((shalf * 4 + j) ^ sswz) * 16);

    auto issue = [&](int c) {
        const int t = c % 3;
        const uint32_t st = smb + t * STG_B;
        const int kb = c * KCH;
#pragma unroll
        for (int j = 0; j < 4; j++) {
            const int e = (shalf * 4 + j) * 4;
            cp16(st + T_A32 + dof[j], aR + kb + e);
            cp16(st + T_B32 + dof[j], bR + kb + e);
        }
        cp_arrive(FILL + 8 * t);
    };

    // Compute geometry.
    const int mBase = (wid & 3) * 32;
    const int nBase = (wid >> 2) * 64;
    const int l7 = lane & 7;
    const int b3 = (lane >> 3) & 1;
    const int b4 = lane >> 4;
    // A rows (per mf): base + b3*8 + l7 ; chunk(ks) = 2ks + b4.
    uint32_t aRow128[2], aSwz[2];
#pragma unroll
    for (int mf = 0; mf < 2; mf++) {
        const int r = mBase + mf * 16 + b3 * 8 + l7;
        aRow128[mf] = r * 128;
        aSwz[mf] = r & 7;
    }
    // B rows (per nb4 group of 16 n-cols): nBase + nb4*16 + b4*8 + l7 ;
    // chunk(ks) = 2ks + b3.
    uint32_t bRow128[4], bSwz[4];
#pragma unroll
    for (int nb4 = 0; nb4 < 4; nb4++) {
        const int r = nBase + nb4 * 16 + b4 * 8 + l7;
        bRow128[nb4] = r * 128;
        bSwz[nb4] = r & 7;
    }

    issue(0);
    issue(1);
    for (int c = 0; c < NCH; c++) {
        const int s = c % 3;
        const int u = c / 3;
        mbar_wait(FILL + 8 * s, (uint32_t)(u & 1));

        const uint32_t stA = smb + s * STG_B + T_A32;
        const uint32_t stB = smb + s * STG_B + T_B32;

#pragma unroll
        for (int ks = 0; ks < 4; ks++) {
            uint32_t af[2][4];
#pragma unroll
            for (int mf = 0; mf < 2; mf++) {
                const uint32_t ch = (uint32_t)(2 * ks + b4);
                ldsm4(af[mf], stA + aRow128[mf] + ((ch ^ aSwz[mf]) << 4));
            }
            uint32_t bf[4][4];
#pragma unroll
            for (int nb4 = 0; nb4 < 4; nb4++) {
                const uint32_t ch = (uint32_t)(2 * ks + b3);
                ldsm4(bf[nb4], stB + bRow128[nb4] + ((ch ^ bSwz[nb4]) << 4));
            }
            if (ks == 3) {
                // Stage fully consumed: free it, then refill with chunk c+2.
                if (lane == 0) mbar_arrive(FREE + 8 * s);
                if (c + 2 < NCH) {
                    const int t = (c + 2) % 3;
                    const int v = (c + 2) / 3;
                    if (v > 0) mbar_wait(FREE + 8 * t, (uint32_t)((v - 1) & 1));
                    issue(c + 2);
                }
            }
#pragma unroll
            for (int nb4 = 0; nb4 < 4; nb4++)
#pragma unroll
                for (int mf = 0; mf < 2; mf++) {
                    mma_tf32(acc[mf][nb4 * 2 + 0], af[mf], bf[nb4][0], bf[nb4][1]);
                    mma_tf32(acc[mf][nb4 * 2 + 1], af[mf], bf[nb4][2], bf[nb4][3]);
                }
        }
    }
}

// ---------------------------------------------------------------------------
// Kernel 1: fused window-partition + QKV GEMM (tf32); epilogue writes q/k/v
// as bf16 hi/lo into padded per-(window,head) layouts for the mma attention.
// ---------------------------------------------------------------------------
__global__ __launch_bounds__(256, 2) void k_qkv_mma(
    const float* __restrict__ qb, const float* __restrict__ vb)
{
    extern __shared__ char sm[];
    const uint32_t smb = smem_u32(sm);
    const int tid = threadIdx.x;
    const int lane = tid & 31, wid = tid >> 5;
    const int bn = blockIdx.x, bm = blockIdx.y;
    const int m0 = bm * 128, n0 = bn * 128;

    long aoff;
    {
        const int srow = tid >> 1;
        const int am = m0 + srow;
        const int wwin = am / NT;
        const int nn = am - wwin * NT;
        const int bimg = wwin >> 4, wi = wwin & 15;
        const int rr = (wi >> 2) * WSZ + nn / WSZ;
        const int cc = (wi & 3) * WSZ + nn % WSZ;
        aoff = ((long)bimg * 3136 + (long)rr * 56 + cc) * CDIM;
    }
    const long boff = (long)(n0 + (tid >> 1)) * CDIM;

    float acc[2][8][4];
#pragma unroll
    for (int a = 0; a < 2; a++)
#pragma unroll
        for (int b = 0; b < 8; b++)
#pragma unroll
            for (int c = 0; c < 4; c++) acc[a][b][c] = 0.f;

    gemm_main(smb, g_x32 + aoff, g_w32 + boff, acc);

    // Epilogue: split-bf16 scatter into padded q/k/v.
    const int m_base = (wid & 3) * 32, n_base = (wid >> 2) * 64;
    const int qrow = lane >> 2, qcol = (lane & 3) * 2;
    const int part = n0 / CDIM;              // 0:q 1:k 2:v
    const int jrbase = n0 - part * CDIM + n_base;
    const int hh = jrbase >> 6;
    __nv_bfloat16* dhi = (part == 0) ? g_qhi : (part == 1) ? g_khi : g_vhi;
    __nv_bfloat16* dlo = (part == 0) ? g_qlo : (part == 1) ? g_klo : g_vlo;
    const int rstr = (part == 0) ? MP : NP;

#pragma unroll
    for (int mf = 0; mf < 2; mf++)
#pragma unroll
        for (int half = 0; half < 2; half++) {
            const int rl = m_base + mf * 16 + half * 8 + qrow;
            const int m = m0 + rl;
            const int w2 = m / NT, n2 = m - w2 * NT;
            const long rb = (((long)w2 * NHD + hh) * rstr + n2) * HD;
#pragma unroll
            for (int nf = 0; nf < 8; nf++) {
                const int dd = nf * 8 + qcol;
                float vx = acc[mf][nf][half * 2 + 0];
                float vy = acc[mf][nf][half * 2 + 1];
                const int jr = jrbase + dd;
                if (part == 0) {
                    vx = (vx + qb[jr]) * 0.125f;
                    vy = (vy + qb[jr + 1]) * 0.125f;
                } else if (part == 2) {
                    vx += vb[jr]; vy += vb[jr + 1];
                }
                uint32_t h, l;
                split2(vx, vy, h, l);
                *(uint32_t*)(dhi + rb + dd) = h;
                *(uint32_t*)(dlo + rb + dd) = l;
            }
        }
}

// ---------------------------------------------------------------------------
// Kernel 2: windowed attention via split-bf16 mma.sync (R13 exact layout);
// epilogue emits tf32-rounded fp32 for the tf32 projection GEMM.
// ---------------------------------------------------------------------------
__global__ __launch_bounds__(224, 1) void k_attn_mma(const float* __restrict__ table)
{
    extern __shared__ char sm[];
    const uint32_t smb = smem_u32(sm);
    float* tbs = (float*)(sm + A_TB);
    const int w = blockIdx.x, h = blockIdx.y;
    const int tid = threadIdx.x;
    const int lane = tid & 31, wid = tid >> 5;   // wid 0..6
    const int lr = lane & 15, lh = lane >> 4;

    // --- cooperative load of Q/K/V hi+lo into swizzled smem ---
    {
        const long qb = ((long)w * NHD + h) * MP * HD;
        const long kb = ((long)w * NHD + h) * NP * HD;
        for (int idx = tid; idx < MP * 8; idx += 224) {
            const int row = idx >> 3, c = idx & 7;
            const uint32_t off = row * 128 + ((c ^ (row & 7)) << 4);
            const long go = qb + row * 64 + c * 8;
            cp16(smb + A_QHI + off, g_qhi + go);
            cp16(smb + A_QLO + off, g_qlo + go);
        }
        for (int idx = tid; idx < NP * 8; idx += 224) {
            const int row = idx >> 3, c = idx & 7;
            const uint32_t off = row * 128 + ((c ^ (row & 7)) << 4);
            const long go = kb + row * 64 + c * 8;
            cp16(smb + A_KHI + off, g_khi + go);
            cp16(smb + A_KLO + off, g_klo + go);
            cp16(smb + A_VHI + off, g_vhi + go);
            cp16(smb + A_VLO + off, g_vlo + go);
        }
        cp_commit();
        for (int t = tid; t < 729; t += 224) tbs[t] = table[t * NHD + h];
        cp_wait0();
    }
    __syncthreads();

    // --- preload Q fragments (rows wid*32 .. +31) ---
    uint32_t qfh[2][4][4], qfl[2][4][4];
#pragma unroll
    for (int mf = 0; mf < 2; mf++)
#pragma unroll
        for (int s = 0; s < 4; s++) {
            const int row = wid * 32 + mf * 16 + lr;
            const uint32_t off = row * 128 + (((2 * s + lh) ^ (row & 7)) << 4);
            ldsm4(qfh[mf][s], smb + A_QHI + off);
            ldsm4(qfl[mf][s], smb + A_QLO + off);
        }

    // --- per-thread row info (4 rows: [mf][rh]) ---
    int rbias[2][2];
    bool rok[2][2];
    const int g = lane >> 2;
#pragma unroll
    for (int mf = 0; mf < 2; mf++)
#pragma unroll
        for (int rh = 0; rh < 2; rh++) {
            const int r = wid * 32 + mf * 16 + rh * 8 + g;
            rok[mf][rh] = (r < NT);
            const int iy = r / WSZ, ix = r - (r / WSZ) * WSZ;
            rbias[mf][rh] = iy * 27 + ix + 13 * 28;
        }

    float mM[2][2], lL[2][2];
    float o[2][8][4];
#pragma unroll
    for (int mf = 0; mf < 2; mf++)
#pragma unroll
        for (int rh = 0; rh < 2; rh++) { mM[mf][rh] = -1e30f; lL[mf][rh] = 0.f; }
#pragma unroll
    for (int a = 0; a < 2; a++)
#pragma unroll
        for (int b = 0; b < 8; b++)
#pragma unroll
            for (int c = 0; c < 4; c++) o[a][b][c] = 0.f;

    const int cbase = 2 * (lane & 3);

    for (int it = 0; it < 13; it++) {
        // K fragments for this 16-key tile.
        uint32_t kfh[4][4], kfl[4][4];
#pragma unroll
        for (int s = 0; s < 4; s++) {
            const int row = it * 16 + lr;
            const uint32_t off = row * 128 + (((2 * s + lh) ^ (row & 7)) << 4);
            ldsm4(kfh[s], smb + A_KHI + off);
            ldsm4(kfl[s], smb + A_KLO + off);
        }
        // S = Q K^T (3-term split), fp32 accum.
        float sc[2][2][4];
#pragma unroll
        for (int mf = 0; mf < 2; mf++)
#pragma unroll
            for (int q = 0; q < 2; q++)
#pragma unroll
                for (int e = 0; e < 4; e++) sc[mf][q][e] = 0.f;
#pragma unroll
        for (int s = 0; s < 4; s++)
#pragma unroll
            for (int q = 0; q < 2; q++)
#pragma unroll
                for (int mf = 0; mf < 2; mf++) {
                    float* d = sc[mf][q];
                    mma16816(d, qfh[mf][s], kfh[s][q], kfh[s][q + 2]);
                    mma16816(d, qfh[mf][s], kfl[s][q], kfl[s][q + 2]);
                    mma16816(d, qfl[mf][s], kfh[s][q], kfh[s][q + 2]);
                }

        // Bias gather + mask.
        int cidx[2][2];
        bool cok[2][2];
#pragma unroll
        for (int q = 0; q < 2; q++)
#pragma unroll
            for (int e1 = 0; e1 < 2; e1++) {
                const int c = it * 16 + q * 8 + cbase + e1;
                cok[q][e1] = (c < NT);
                const int jy = c / WSZ;
                cidx[q][e1] = jy * 27 + (c - jy * WSZ);
            }
#pragma unroll
        for (int mf = 0; mf < 2; mf++)
#pragma unroll
            for (int q = 0; q < 2; q++)
#pragma unroll
                for (int e = 0; e < 4; e++) {
                    const int rh = e >> 1, e1 = e & 1;
                    if (!cok[q][e1]) sc[mf][q][e] = -1e30f;
                    else if (rok[mf][rh])
                        sc[mf][q][e] += tbs[rbias[mf][rh] - cidx[q][e1]];
                }

        // Online softmax per row group.
#pragma unroll
        for (int mf = 0; mf < 2; mf++)
#pragma unroll
            for (int rh = 0; rh < 2; rh++) {
                float vmax = fmaxf(fmaxf(sc[mf][0][2 * rh], sc[mf][0][2 * rh + 1]),
                                   fmaxf(sc[mf][1][2 * rh], sc[mf][1][2 * rh + 1]));
                vmax = fmaxf(vmax, __shfl_xor_sync(0xffffffffu, vmax, 1));
                vmax = fmaxf(vmax, __shfl_xor_sync(0xffffffffu, vmax, 2));
                const float mn = fmaxf(mM[mf][rh], vmax);
                const float corr = __expf(mM[mf][rh] - mn);
                mM[mf][rh] = mn;
                float rs = 0.f;
#pragma unroll
                for (int q = 0; q < 2; q++)
#pragma unroll
                    for (int e1 = 0; e1 < 2; e1++) {
                        const float p = __expf(sc[mf][q][2 * rh + e1] - mn);
                        sc[mf][q][2 * rh + e1] = p;
                        rs += p;
                    }
                rs += __shfl_xor_sync(0xffffffffu, rs, 1);
                rs += __shfl_xor_sync(0xffffffffu, rs, 2);
                lL[mf][rh] = lL[mf][rh] * corr + rs;
#pragma unroll
                for (int n = 0; n < 8; n++) {
                    o[mf][n][2 * rh + 0] *= corr;
                    o[mf][n][2 * rh + 1] *= corr;
                }
            }

        // P -> A-fragments (hi/lo).  C-frag(m16n16) == A-frag(m16k16).
        uint32_t pfh[2][4], pfl[2][4];
#pragma unroll
        for (int mf = 0; mf < 2; mf++) {
            split2(sc[mf][0][0], sc[mf][0][1], pfh[mf][0], pfl[mf][0]);
            split2(sc[mf][0][2], sc[mf][0][3], pfh[mf][1], pfl[mf][1]);
            split2(sc[mf][1][0], sc[mf][1][1], pfh[mf][2], pfl[mf][2]);
            split2(sc[mf][1][2], sc[mf][1][3], pfh[mf][3], pfl[mf][3]);
        }

        // O += P V (V via ldmatrix.trans; 3-term split).
#pragma unroll
        for (int gg = 0; gg < 4; gg++) {
            const int row = it * 16 + lr;
            const uint32_t off = row * 128 + (((2 * gg + lh) ^ (row & 7)) << 4);
            uint32_t vfh[4], vfl[4];
            ldsm4t(vfh, smb + A_VHI + off);
            ldsm4t(vfl, smb + A_VLO + off);
#pragma unroll
            for (int q = 0; q < 2; q++)
#pragma unroll
                for (int mf = 0; mf < 2; mf++) {
                    float* d = o[mf][gg * 2 + q];
                    mma16816(d, pfh[mf], vfh[2 * q], vfh[2 * q + 1]);
                    mma16816(d, pfh[mf], vfl[2 * q], vfl[2 * q + 1]);
                    mma16816(d, pfl[mf], vfh[2 * q], vfh[2 * q + 1]);
                }
        }
    }

    // Epilogue: divide by l, window-reverse, emit tf32-rounded fp32.
    const int bimg = w >> 4, wi = w & 15;
#pragma unroll
    for (int mf = 0; mf < 2; mf++)
#pragma unroll
        for (int rh = 0; rh < 2; rh++) {
            if (!rok[mf][rh]) continue;
            const int r = wid * 32 + mf * 16 + rh * 8 + g;
            const int iy = r / WSZ, ix = r - (r / WSZ) * WSZ;
            const int rr = (wi >> 2) * WSZ + iy;
            const int cc = (wi & 3) * WSZ + ix;
            const long ob = ((long)bimg * 3136 + (long)rr * 56 + cc) * CDIM + h * HD;
            const float inv = 1.f / lL[mf][rh];
#pragma unroll
            for (int n = 0; n < 8; n++) {
                const int col = n * 8 + cbase;
                *(float2*)(g_a32 + ob + col) = make_float2(
                    tf32r(o[mf][n][2 * rh + 0] * inv),
                    tf32r(o[mf][n][2 * rh + 1] * inv));
            }
        }
}

// ---------------------------------------------------------------------------
// Kernel 3: output projection GEMM (tf32; reads g_a32, g_pw32)
// ---------------------------------------------------------------------------
__global__ __launch_bounds__(256, 2) void k_proj_mma(
    const float* __restrict__ pb, float* __restrict__ out)
{
    extern __shared__ char sm[];
    const uint32_t smb = smem_u32(sm);
    const int tid = threadIdx.x;
    const int lane = tid & 31, wid = tid >> 5;
    const int bn = blockIdx.x, bm = blockIdx.y;
    const int m0 = bm * 128, n0 = bn * 128;

    const long aoff = (long)(m0 + (tid >> 1)) * CDIM;
    const long boff = (long)(n0 + (tid >> 1)) * CDIM;

    float acc[2][8][4];
#pragma unroll
    for (int a = 0; a < 2; a++)
#pragma unroll
        for (int b = 0; b < 8; b++)
#pragma unroll
            for (int c = 0; c < 4; c++) acc[a][b][c] = 0.f;

    gemm_main(smb, g_a32 + aoff, g_pw32 + boff, acc);

    const int m_base = (wid & 3) * 32, n_base = (wid >> 2) * 64;
    const int qrow = lane >> 2, qcol = (lane & 3) * 2;

#pragma unroll
    for (int mf = 0; mf < 2; mf++)
#pragma unroll
        for (int half = 0; half < 2; half++) {
            const int rl = m_base + mf * 16 + half * 8 + qrow;
            const int m = m0 + rl;
            float* rp = out + (long)m * CDIM + n0 + n_base;
#pragma unroll
            for (int nf = 0; nf < 8; nf++) {
                const int dd = nf * 8 + qcol;
                const float2 bias = *(const float2*)(pb + n0 + n_base + dd);
                *(float2*)(rp + dd) = make_float2(
                    acc[mf][nf][half * 2 + 0] + bias.x,
                    acc[mf][nf][half * 2 + 1] + bias.y);
            }
        }
}

// ---------------------------------------------------------------------------
extern "C" void kernel_launch(void* const* d_in, const int* in_sizes, int n_in,
                              void* d_out, int out_size)
{
    const float* x    = (const float*)d_in[0];
    const float* qkvw = (const float*)d_in[1];
    const float* qb   = (const float*)d_in[2];
    const float* vb   = (const float*)d_in[3];
    const float* tbl  = (const float*)d_in[4];
    const float* pw   = (const float*)d_in[5];
    const float* pb   = (const float*)d_in[6];
    float* out = (float*)d_out;

    cudaFuncSetAttribute(k_qkv_mma,
                         cudaFuncAttributeMaxDynamicSharedMemorySize, SMEM_TOT);
    cudaFuncSetAttribute(k_proj_mma,
                         cudaFuncAttributeMaxDynamicSharedMemorySize, SMEM_TOT);
    cudaFuncSetAttribute(k_attn_mma,
                         cudaFuncAttributeMaxDynamicSharedMemorySize, SMEM_ATT);

    float *x32, *w32, *pw32;
    cudaGetSymbolAddress((void**)&x32, g_x32);
    cudaGetSymbolAddress((void**)&w32, g_w32);
    cudaGetSymbolAddress((void**)&pw32, g_pw32);

    // Pre-round fp32 operands to tf32 (rna).
    {
        const long n4x = (long)M1 * CDIM / 4;
        k_cvt32<<<(unsigned)((n4x + 255) / 256), 256>>>(x, x32, n4x);
        const long n4w = (long)QKVN * CDIM / 4;
        k_cvt32<<<(unsigned)((n4w + 255) / 256), 256>>>(qkvw, w32, n4w);
        const long n4p = (long)CDIM * CDIM / 4;
        k_cvt32<<<(unsigned)((n4p + 255) / 256), 256>>>(pw, pw32, n4p);
    }

    dim3 g1(QKVN / 128, M1 / 128);   // (18, 392)
    k_qkv_mma<<<g1, 256, SMEM_TOT>>>(qb, vb);

    dim3 g2(NWIN, NHD);              // (256, 12)
    k_attn_mma<<<g2, 224, SMEM_ATT>>>(tbl);

    dim3 g3(CDIM / 128, M1 / 128);   // (6, 392)
    k_proj_mma<<<g3, 256, SMEM_TOT>>>(pb, out);
}